// round 6
// baseline (speedup 1.0000x reference)
#include <cuda_runtime.h>
#include <cstddef>

#define T_  512
#define B_  64
#define H_  512
#define G3  1536   // 3*H

// ---------------- device scratch (no allocations allowed) ----------------
__device__ float g_gi[(size_t)T_ * B_ * G3];   // input projection (one layer at a time)
__device__ float g_y0[(size_t)T_ * B_ * H_];   // layer-0 output sequence
__device__ float g_h[B_ * H_];                 // current hidden state
__device__ float g_ghp[4 * B_ * G3];           // k-split partial gh
__device__ float g_dummy[B_ * H_];             // fallback hlast sink
__device__ unsigned g_count = 0;
__device__ volatile unsigned g_gen = 0;

#define NB_REC 96u

// ---------------- grid barrier (all 96 CTAs co-resident) ----------------
__device__ __forceinline__ void gridbar() {
    __threadfence();
    __syncthreads();
    if (threadIdx.x == 0) {
        unsigned gen = g_gen;
        unsigned prev = atomicAdd(&g_count, 1u);
        if (prev == NB_REC - 1u) {
            g_count = 0u;
            __threadfence();
            g_gen = gen + 1u;
        } else {
            while (g_gen == gen) { __nanosleep(32); }
        }
    }
    __syncthreads();
    __threadfence();
}

// ---------------- dual block reduction over 256 threads ----------------
__device__ __forceinline__ void blockReduce2(float& a, float& b, float* red) {
    int tid = threadIdx.x, lane = tid & 31, wid = tid >> 5;
#pragma unroll
    for (int o = 16; o; o >>= 1) {
        a += __shfl_down_sync(0xffffffffu, a, o);
        b += __shfl_down_sync(0xffffffffu, b, o);
    }
    if (lane == 0) { red[wid] = a; red[8 + wid] = b; }
    __syncthreads();
    if (tid < 32) {
        a = (lane < 8) ? red[lane] : 0.0f;
        b = (lane < 8) ? red[8 + lane] : 0.0f;
#pragma unroll
        for (int o = 4; o; o >>= 1) {
            a += __shfl_down_sync(0xffffffffu, a, o);
            b += __shfl_down_sync(0xffffffffu, b, o);
        }
        if (lane == 0) { red[16] = a; red[17] = b; }
    }
    __syncthreads();
    a = red[16]; b = red[17];
    __syncthreads();
}

// ---------------- set hidden state ----------------
__global__ void k_seth(const float* __restrict__ h0) {
    int i = blockIdx.x * blockDim.x + threadIdx.x;
    g_h[i] = h0[i];
}

// ---------------- input projection GEMM ----------------
// g_gi[m][n] = X[m][:] . W[n][:] + bias[n];  M=32768, N=1536, K=512
// 64x64 tile, BK=32, 256 threads, 4x4 strided micro-tiles.
__global__ void __launch_bounds__(256) k_gemm_in(
    const float* __restrict__ Xe, int x_internal,
    const float* __restrict__ W, const float* __restrict__ bias)
{
    __shared__ float xs[32 * 65];
    __shared__ float ws[32 * 65];
    const float* X = x_internal ? g_y0 : Xe;

    const int n0 = blockIdx.x * 64;
    const int m0 = blockIdx.y * 64;
    const int tid = threadIdx.x;
    const int tx = tid & 15, ty = tid >> 4;

    float acc[4][4];
#pragma unroll
    for (int i = 0; i < 4; i++)
#pragma unroll
        for (int j = 0; j < 4; j++) acc[i][j] = 0.0f;

    const float* Xp = X + (size_t)m0 * 512;
    const float* Wp = W + (size_t)n0 * 512;

    for (int kb = 0; kb < 512; kb += 32) {
#pragma unroll
        for (int r = 0; r < 8; r++) {
            int idx = tid + r * 256;
            int mm = idx >> 5, kk = idx & 31;
            xs[kk * 65 + mm] = Xp[(size_t)mm * 512 + kb + kk];
            ws[kk * 65 + mm] = Wp[(size_t)mm * 512 + kb + kk];
        }
        __syncthreads();
#pragma unroll 8
        for (int kk = 0; kk < 32; kk++) {
            float a[4], w[4];
#pragma unroll
            for (int i = 0; i < 4; i++) a[i] = xs[kk * 65 + ty + 16 * i];
#pragma unroll
            for (int j = 0; j < 4; j++) w[j] = ws[kk * 65 + tx + 16 * j];
#pragma unroll
            for (int i = 0; i < 4; i++)
#pragma unroll
                for (int j = 0; j < 4; j++)
                    acc[i][j] += a[i] * w[j];
        }
        __syncthreads();
    }
#pragma unroll
    for (int i = 0; i < 4; i++) {
        int m = m0 + ty + 16 * i;
#pragma unroll
        for (int j = 0; j < 4; j++) {
            int n = n0 + tx + 16 * j;
            g_gi[(size_t)m * G3 + n] = acc[i][j] + bias[n];
        }
    }
}

// ---------------- persistent recurrence kernel ----------------
// 96 CTAs = 24 n-tiles x 4 k-chunks; 256 threads.
// Dynamic smem: wsm[128*65] (Whh tile, cached across all steps) + hs[128*65].
__global__ void __launch_bounds__(256, 1) k_rec(
    const float* __restrict__ Whh, const float* __restrict__ bhh,
    const float* __restrict__ lng, const float* __restrict__ lnb,
    float* __restrict__ y_ext, int y_internal, float* __restrict__ hlast)
{
    extern __shared__ float sm[];
    float* wsm = sm;              // [128*65]
    float* hs  = sm + 128 * 65;   // [128*65]

    const int tid = threadIdx.x;
    const int bx  = blockIdx.x;
    const int nt  = bx % 24;
    const int kc  = bx / 24;
    const int n0  = nt * 64;
    const int k0  = kc * 128;
    float* y = y_internal ? g_y0 : y_ext;

    // Stage Whh tile once: wsm[kk][n] (padded row 65)
#pragma unroll
    for (int r = 0; r < 32; r++) {
        int idx = tid + r * 256;
        int n = idx >> 7, kk = idx & 127;
        wsm[kk * 65 + n] = Whh[(size_t)(n0 + n) * 512 + k0 + kk];
    }

    const int tx = tid & 15, ty = tid >> 4;

    for (int t = 0; t < T_; t++) {
        __syncthreads();  // covers wsm staging (t=0) + hs reuse by phase 2 (t>0)
#pragma unroll
        for (int r = 0; r < 32; r++) {
            int idx = tid + r * 256;
            int b = idx >> 7, kk = idx & 127;
            hs[kk * 65 + b] = g_h[b * 512 + k0 + kk];
        }
        __syncthreads();

        float acc[4][4];
#pragma unroll
        for (int i = 0; i < 4; i++)
#pragma unroll
            for (int j = 0; j < 4; j++) acc[i][j] = 0.0f;

#pragma unroll 8
        for (int kk = 0; kk < 128; kk++) {
            float a[4], w[4];
#pragma unroll
            for (int i = 0; i < 4; i++) a[i] = hs[kk * 65 + ty + 16 * i];
#pragma unroll
            for (int j = 0; j < 4; j++) w[j] = wsm[kk * 65 + tx + 16 * j];
#pragma unroll
            for (int i = 0; i < 4; i++)
#pragma unroll
                for (int j = 0; j < 4; j++)
                    acc[i][j] += a[i] * w[j];
        }

#pragma unroll
        for (int i = 0; i < 4; i++) {
            int b = ty + 16 * i;
#pragma unroll
            for (int j = 0; j < 4; j++)
                g_ghp[(size_t)(kc * 64 + b) * G3 + (n0 + tx + 16 * j)] = acc[i][j];
        }

        gridbar();

        // ---------- phase 2: CTA b handles batch-row b ----------
        if (bx < B_) {
            const int b = bx;
            float* A   = hs;           // pre_r
            float* Bv  = hs + 512;     // pre_i -> inputgate
            float* Cc  = hs + 1024;    // gh_n -> pre_n
            float* Dd  = hs + 1536;    // gi_n
            float* red = hs + 2048;    // 18 floats
            const float* git = g_gi + ((size_t)t * B_ + b) * G3;

            for (int j = tid; j < 512; j += 256) {
                float s_r = bhh[j], s_i = bhh[512 + j], s_n = bhh[1024 + j];
#pragma unroll
                for (int kq = 0; kq < 4; kq++) {
                    const float* p = g_ghp + (size_t)(kq * 64 + b) * G3;
                    s_r += p[j]; s_i += p[512 + j]; s_n += p[1024 + j];
                }
                A[j]  = git[j] + s_r;
                Bv[j] = git[512 + j] + s_i;
                Cc[j] = s_n;
                Dd[j] = git[1024 + j];
            }
            __syncthreads();

            float sr = 0.f, qr = 0.f, si = 0.f, qi = 0.f;
            for (int j = tid; j < 512; j += 256) {
                float v = A[j];  sr += v; qr += v * v;
                v = Bv[j];       si += v; qi += v * v;
            }
            blockReduce2(sr, qr, red);
            blockReduce2(si, qi, red);
            const float inv = 1.0f / 512.0f;
            float mur = sr * inv, rr = rsqrtf(qr * inv - mur * mur + 1e-5f);
            float mui = si * inv, ri = rsqrtf(qi * inv - mui * mui + 1e-5f);

            for (int j = tid; j < 512; j += 256) {
                float xr = (A[j] - mur) * rr * lng[j] + lnb[j];
                float rg = 1.0f / (1.0f + __expf(-xr));
                float xi = (Bv[j] - mui) * ri * lng[512 + j] + lnb[512 + j];
                Bv[j] = 1.0f / (1.0f + __expf(-xi));
                Cc[j] = Dd[j] + rg * Cc[j];
            }
            __syncthreads();

            float sn = 0.f, qn = 0.f;
            for (int j = tid; j < 512; j += 256) { float v = Cc[j]; sn += v; qn += v * v; }
            blockReduce2(sn, qn, red);
            float mun = sn * inv, rn = rsqrtf(qn * inv - mun * mun + 1e-5f);

            for (int j = tid; j < 512; j += 256) {
                float xn = (Cc[j] - mun) * rn * lng[1024 + j] + lnb[1024 + j];
                float ng = tanhf(xn);
                float hold = g_h[b * 512 + j];
                float hy = ng + Bv[j] * (hold - ng);
                g_h[b * 512 + j] = hy;
                y[((size_t)t * B_ + b) * H_ + j] = hy;
                if (t == T_ - 1) hlast[b * 512 + j] = hy;
            }
        }

        gridbar();
    }
}

// ---------------- launcher ----------------
extern "C" void kernel_launch(void* const* d_in, const int* in_sizes, int n_in,
                              void* d_out, int out_size) {
    (void)in_sizes; (void)n_in;
    const float* x   = (const float*)d_in[0];   // (T,B,D)
    const float* h0  = (const float*)d_in[1];   // (L,B,H)
    const float* Wih = (const float*)d_in[2];   // (L,3H,D)
    const float* bih = (const float*)d_in[3];   // (L,3H)
    const float* Whh = (const float*)d_in[4];   // (L,3H,H)
    const float* bhh = (const float*)d_in[5];   // (L,3H)
    const float* lng = (const float*)d_in[6];   // (L,3,H)
    const float* lnb = (const float*)d_in[7];   // (L,3,H)
    float* out = (float*)d_out;

    const size_t TBH = (size_t)T_ * B_ * H_;    // 16,777,216
    const size_t LBH = (size_t)2 * B_ * H_;     // 65,536
    bool has_hl = ((size_t)out_size >= TBH + LBH);

    float* hl_dummy = nullptr;
    cudaGetSymbolAddress((void**)&hl_dummy, g_dummy);
    float* hl0 = has_hl ? out + TBH          : hl_dummy;
    float* hl1 = has_hl ? out + TBH + B_*H_  : hl_dummy;

    const int smem_rec = 2 * 128 * 65 * (int)sizeof(float);  // 66,560 B
    cudaFuncSetAttribute(k_rec, cudaFuncAttributeMaxDynamicSharedMemorySize, smem_rec);

    dim3 gg(G3 / 64, (T_ * B_) / 64);  // (24, 512)

    // ----- layer 0 -----
    k_gemm_in<<<gg, 256>>>(x, 0, Wih, bih);
    k_seth<<<(B_ * H_) / 256, 256>>>(h0);
    k_rec<<<NB_REC, 256, smem_rec>>>(Whh, bhh, lng, lnb, out, /*y_internal=*/1, hl0);

    // ----- layer 1 -----
    k_gemm_in<<<gg, 256>>>(nullptr, 1, Wih + (size_t)G3 * H_, bih + G3);
    k_seth<<<(B_ * H_) / 256, 256>>>(h0 + B_ * H_);
    k_rec<<<NB_REC, 256, smem_rec>>>(Whh + (size_t)G3 * H_, bhh + G3,
                                     lng + G3, lnb + G3,
                                     out, /*y_internal=*/0, hl1);
}

// round 7
// speedup vs baseline: 1.0924x; 1.0924x over previous
#include <cuda_runtime.h>
#include <cstddef>

#define T_  512
#define B_  64
#define H_  512
#define G3  1536   // 3*H

// ---------------- device scratch ----------------
__device__ float g_gi[(size_t)T_ * B_ * G3];
__device__ float g_y0[(size_t)T_ * B_ * H_];
__device__ float g_h[B_ * H_];
__device__ float g_ghp[4 * B_ * G3];
__device__ float g_dummy[B_ * H_];
__device__ unsigned g_count = 0;
__device__ volatile unsigned g_gen = 0;

#define NB_REC 96u

// packed fp32x2 FMA: d.lo += a.lo*b.lo ; d.hi += a.hi*b.hi  (bit-exact 2x FFMA)
__device__ __forceinline__ void ffma2(unsigned long long& d,
                                      unsigned long long a,
                                      unsigned long long b) {
    asm("fma.rn.f32x2 %0, %1, %2, %0;" : "+l"(d) : "l"(a), "l"(b));
}

__device__ __forceinline__ float acc_sum(unsigned long long v) {
    float2 f;
    asm("mov.b64 {%0, %1}, %2;" : "=f"(f.x), "=f"(f.y) : "l"(v));
    return f.x + f.y;
}

// ---------------- grid barrier (96 CTAs co-resident) ----------------
__device__ __forceinline__ void gridbar() {
    __threadfence();
    __syncthreads();
    if (threadIdx.x == 0) {
        unsigned gen = g_gen;
        unsigned prev = atomicAdd(&g_count, 1u);
        if (prev == NB_REC - 1u) {
            g_count = 0u;
            __threadfence();
            g_gen = gen + 1u;
        } else {
            while (g_gen == gen) { }
        }
    }
    __syncthreads();
    __threadfence();
}

// ---------------- dual block reduction over 256 threads ----------------
__device__ __forceinline__ void blockReduce2(float& a, float& b, float* red) {
    int tid = threadIdx.x, lane = tid & 31, wid = tid >> 5;
#pragma unroll
    for (int o = 16; o; o >>= 1) {
        a += __shfl_down_sync(0xffffffffu, a, o);
        b += __shfl_down_sync(0xffffffffu, b, o);
    }
    if (lane == 0) { red[wid] = a; red[8 + wid] = b; }
    __syncthreads();
    if (tid < 32) {
        a = (lane < 8) ? red[lane] : 0.0f;
        b = (lane < 8) ? red[8 + lane] : 0.0f;
#pragma unroll
        for (int o = 4; o; o >>= 1) {
            a += __shfl_down_sync(0xffffffffu, a, o);
            b += __shfl_down_sync(0xffffffffu, b, o);
        }
        if (lane == 0) { red[16] = a; red[17] = b; }
    }
    __syncthreads();
    a = red[16]; b = red[17];
    __syncthreads();
}

__global__ void k_seth(const float* __restrict__ h0) {
    int i = blockIdx.x * blockDim.x + threadIdx.x;
    g_h[i] = h0[i];
}

// ---------------- input projection GEMM (f32x2) ----------------
// g_gi[m][n] = X[m][:].W[n][:] + bias[n];  M=32768, N=1536, K=512
// 64x64 tile, BK=64, 256 thr, micro m=ty+16i / n=tx+16j, k-packed f32x2.
#define XS_STRIDE 68   // 64 + 4 pad; 68*4=272=17*16 -> 16B-aligned rows
__global__ void __launch_bounds__(256) k_gemm_in(
    const float* __restrict__ Xe, int x_internal,
    const float* __restrict__ W, const float* __restrict__ bias)
{
    __shared__ float xs[64 * XS_STRIDE];
    __shared__ float ws[64 * XS_STRIDE];
    const float* X = x_internal ? g_y0 : Xe;

    const int n0 = blockIdx.x * 64;
    const int m0 = blockIdx.y * 64;
    const int tid = threadIdx.x;
    const int tx = tid & 15, ty = tid >> 4;

    unsigned long long acc[4][4];
#pragma unroll
    for (int i = 0; i < 4; i++)
#pragma unroll
        for (int j = 0; j < 4; j++) acc[i][j] = 0ull;

    const float* Xp = X + (size_t)m0 * 512;
    const float* Wp = W + (size_t)n0 * 512;

    int aoff[4], woff[4];
#pragma unroll
    for (int i = 0; i < 4; i++) aoff[i] = (ty + 16 * i) * XS_STRIDE;
#pragma unroll
    for (int j = 0; j < 4; j++) woff[j] = (tx + 16 * j) * XS_STRIDE;

    for (int kb = 0; kb < 512; kb += 64) {
        // stage X and W tiles, k-contiguous rows, float4
#pragma unroll
        for (int r = 0; r < 4; r++) {
            int idx = tid + r * 256;
            int row = idx >> 4, kf4 = (idx & 15) * 4;
            *reinterpret_cast<float4*>(&xs[row * XS_STRIDE + kf4]) =
                *reinterpret_cast<const float4*>(&Xp[(size_t)row * 512 + kb + kf4]);
            *reinterpret_cast<float4*>(&ws[row * XS_STRIDE + kf4]) =
                *reinterpret_cast<const float4*>(&Wp[(size_t)row * 512 + kb + kf4]);
        }
        __syncthreads();

#pragma unroll 4
        for (int k4 = 0; k4 < 64; k4 += 4) {
            ulonglong2 av[4], wv[4];
#pragma unroll
            for (int i = 0; i < 4; i++)
                av[i] = *reinterpret_cast<const ulonglong2*>(&xs[aoff[i] + k4]);
#pragma unroll
            for (int j = 0; j < 4; j++)
                wv[j] = *reinterpret_cast<const ulonglong2*>(&ws[woff[j] + k4]);
#pragma unroll
            for (int i = 0; i < 4; i++)
#pragma unroll
                for (int j = 0; j < 4; j++) {
                    ffma2(acc[i][j], av[i].x, wv[j].x);
                    ffma2(acc[i][j], av[i].y, wv[j].y);
                }
        }
        __syncthreads();
    }

#pragma unroll
    for (int i = 0; i < 4; i++) {
        int m = m0 + ty + 16 * i;
#pragma unroll
        for (int j = 0; j < 4; j++) {
            int n = n0 + tx + 16 * j;
            g_gi[(size_t)m * G3 + n] = acc_sum(acc[i][j]) + bias[n];
        }
    }
}

// ---------------- persistent recurrence kernel (f32x2) ----------------
// 96 CTAs = 24 n-tiles x 4 k-chunks; 256 threads.
// smem: wsm[64][132] (Whh rows, cached all steps) + hs[64][132] (h rows).
#define RS 132   // 128 + 4 pad; 132*4=528=33*16 -> aligned
__global__ void __launch_bounds__(256, 1) k_rec(
    const float* __restrict__ Whh, const float* __restrict__ bhh,
    const float* __restrict__ lng, const float* __restrict__ lnb,
    float* __restrict__ y_ext, int y_internal, float* __restrict__ hlast)
{
    extern __shared__ float sm[];
    float* wsm = sm;             // [64*RS]
    float* hs  = sm + 64 * RS;   // [64*RS]

    const int tid = threadIdx.x;
    const int bx  = blockIdx.x;
    const int nt  = bx % 24;
    const int kc  = bx / 24;
    const int n0  = nt * 64;
    const int k0  = kc * 128;
    float* y = y_internal ? g_y0 : y_ext;

    // stage Whh tile once: wsm[n][kk] = Whh[n0+n][k0+kk]
#pragma unroll
    for (int r = 0; r < 8; r++) {
        int idx = tid + r * 256;
        int n = idx >> 5, kf4 = (idx & 31) * 4;
        *reinterpret_cast<float4*>(&wsm[n * RS + kf4]) =
            *reinterpret_cast<const float4*>(&Whh[(size_t)(n0 + n) * 512 + k0 + kf4]);
    }

    const int tx = tid & 15, ty = tid >> 4;
    int aoff[4], woff[4];
#pragma unroll
    for (int i = 0; i < 4; i++) aoff[i] = (ty + 16 * i) * RS;
#pragma unroll
    for (int j = 0; j < 4; j++) woff[j] = (tx + 16 * j) * RS;

    for (int t = 0; t < T_; t++) {
        // stage h tile: hs[b][kk] = g_h[b][k0+kk]
#pragma unroll
        for (int r = 0; r < 8; r++) {
            int idx = tid + r * 256;
            int b = idx >> 5, kf4 = (idx & 31) * 4;
            *reinterpret_cast<float4*>(&hs[b * RS + kf4]) =
                *reinterpret_cast<const float4*>(&g_h[b * 512 + k0 + kf4]);
        }
        __syncthreads();

        unsigned long long acc[4][4];
#pragma unroll
        for (int i = 0; i < 4; i++)
#pragma unroll
            for (int j = 0; j < 4; j++) acc[i][j] = 0ull;

#pragma unroll 8
        for (int k4 = 0; k4 < 128; k4 += 4) {
            ulonglong2 av[4], wv[4];
#pragma unroll
            for (int i = 0; i < 4; i++)
                av[i] = *reinterpret_cast<const ulonglong2*>(&hs[aoff[i] + k4]);
#pragma unroll
            for (int j = 0; j < 4; j++)
                wv[j] = *reinterpret_cast<const ulonglong2*>(&wsm[woff[j] + k4]);
#pragma unroll
            for (int i = 0; i < 4; i++)
#pragma unroll
                for (int j = 0; j < 4; j++) {
                    ffma2(acc[i][j], av[i].x, wv[j].x);
                    ffma2(acc[i][j], av[i].y, wv[j].y);
                }
        }

#pragma unroll
        for (int i = 0; i < 4; i++) {
            int b = ty + 16 * i;
#pragma unroll
            for (int j = 0; j < 4; j++)
                g_ghp[(size_t)(kc * 64 + b) * G3 + (n0 + tx + 16 * j)] =
                    acc_sum(acc[i][j]);
        }

        gridbar();

        // ---------- phase 2: CTA b handles batch row b ----------
        if (bx < B_) {
            const int b = bx;
            float* A   = hs;           // pre_r
            float* Bv  = hs + 512;     // pre_i -> inputgate
            float* Cc  = hs + 1024;    // gh_n -> pre_n
            float* Dd  = hs + 1536;    // gi_n
            float* red = hs + 2048;    // reduction scratch
            const float* git = g_gi + ((size_t)t * B_ + b) * G3;

            for (int j = tid; j < 512; j += 256) {
                float s_r = bhh[j], s_i = bhh[512 + j], s_n = bhh[1024 + j];
#pragma unroll
                for (int kq = 0; kq < 4; kq++) {
                    const float* p = g_ghp + (size_t)(kq * 64 + b) * G3;
                    s_r += p[j]; s_i += p[512 + j]; s_n += p[1024 + j];
                }
                A[j]  = git[j] + s_r;
                Bv[j] = git[512 + j] + s_i;
                Cc[j] = s_n;
                Dd[j] = git[1024 + j];
            }
            __syncthreads();

            float sr = 0.f, qr = 0.f, si = 0.f, qi = 0.f;
            for (int j = tid; j < 512; j += 256) {
                float v = A[j];  sr += v; qr += v * v;
                v = Bv[j];       si += v; qi += v * v;
            }
            blockReduce2(sr, qr, red);
            blockReduce2(si, qi, red);
            const float inv = 1.0f / 512.0f;
            float mur = sr * inv, rr = rsqrtf(qr * inv - mur * mur + 1e-5f);
            float mui = si * inv, ri = rsqrtf(qi * inv - mui * mui + 1e-5f);

            for (int j = tid; j < 512; j += 256) {
                float xr = (A[j] - mur) * rr * lng[j] + lnb[j];
                float rg = 1.0f / (1.0f + __expf(-xr));
                float xi = (Bv[j] - mui) * ri * lng[512 + j] + lnb[512 + j];
                Bv[j] = 1.0f / (1.0f + __expf(-xi));
                Cc[j] = Dd[j] + rg * Cc[j];
            }
            __syncthreads();

            float sn = 0.f, qn = 0.f;
            for (int j = tid; j < 512; j += 256) { float v = Cc[j]; sn += v; qn += v * v; }
            blockReduce2(sn, qn, red);
            float mun = sn * inv, rn = rsqrtf(qn * inv - mun * mun + 1e-5f);

            for (int j = tid; j < 512; j += 256) {
                float xn = (Cc[j] - mun) * rn * lng[1024 + j] + lnb[1024 + j];
                float ng = tanhf(xn);
                float hold = g_h[b * 512 + j];
                float hy = ng + Bv[j] * (hold - ng);
                g_h[b * 512 + j] = hy;
                y[((size_t)t * B_ + b) * H_ + j] = hy;
                if (t == T_ - 1) hlast[b * 512 + j] = hy;
            }
        }

        gridbar();
    }
}

// ---------------- launcher ----------------
extern "C" void kernel_launch(void* const* d_in, const int* in_sizes, int n_in,
                              void* d_out, int out_size) {
    (void)in_sizes; (void)n_in;
    const float* x   = (const float*)d_in[0];
    const float* h0  = (const float*)d_in[1];
    const float* Wih = (const float*)d_in[2];
    const float* bih = (const float*)d_in[3];
    const float* Whh = (const float*)d_in[4];
    const float* bhh = (const float*)d_in[5];
    const float* lng = (const float*)d_in[6];
    const float* lnb = (const float*)d_in[7];
    float* out = (float*)d_out;

    const size_t TBH = (size_t)T_ * B_ * H_;
    const size_t LBH = (size_t)2 * B_ * H_;
    bool has_hl = ((size_t)out_size >= TBH + LBH);

    float* hl_dummy = nullptr;
    cudaGetSymbolAddress((void**)&hl_dummy, g_dummy);
    float* hl0 = has_hl ? out + TBH           : hl_dummy;
    float* hl1 = has_hl ? out + TBH + B_ * H_ : hl_dummy;

    const int smem_rec = 2 * 64 * RS * (int)sizeof(float);  // 67,584 B
    cudaFuncSetAttribute(k_rec, cudaFuncAttributeMaxDynamicSharedMemorySize, smem_rec);

    dim3 gg(G3 / 64, (T_ * B_) / 64);  // (24, 512)

    // layer 0
    k_gemm_in<<<gg, 256>>>(x, 0, Wih, bih);
    k_seth<<<(B_ * H_) / 256, 256>>>(h0);
    k_rec<<<NB_REC, 256, smem_rec>>>(Whh, bhh, lng, lnb, out, 1, hl0);

    // layer 1
    k_gemm_in<<<gg, 256>>>(nullptr, 1, Wih + (size_t)G3 * H_, bih + G3);
    k_seth<<<(B_ * H_) / 256, 256>>>(h0 + B_ * H_);
    k_rec<<<NB_REC, 256, smem_rec>>>(Whh + (size_t)G3 * H_, bhh + G3,
                                     lng + G3, lnb + G3,
                                     out, 0, hl1);
}